// round 2
// baseline (speedup 1.0000x reference)
#include <cuda_runtime.h>
#include <cstdint>

// DistEmb forward: out[i, :] = table[idx[i], :]
// table: [2_000_000, 128] fp32, idx: [1_048_576] int32 (JAX x64 disabled ->
// jnp.int64 request silently materializes as int32), out: [1_048_576, 128] fp32
//
// One warp per row. Row = 128 floats = 32 float4; lane l moves float4 #l.
// Fully coalesced 512B/warp in and out; idx load is warp-uniform broadcast.

static constexpr int EMB_F4  = 32;   // 128 floats / 4 per float4
static constexpr int THREADS = 256;  // 8 warps / block

__global__ __launch_bounds__(THREADS)
void distemb_gather_kernel(const float4* __restrict__ table,
                           const int* __restrict__ idx,
                           float4* __restrict__ out,
                           int num_ids)
{
    const int gtid = blockIdx.x * THREADS + threadIdx.x;
    const int row  = gtid >> 5;          // warp id = output row
    const int lane = gtid & 31;
    if (row >= num_ids) return;

    const int src = __ldg(&idx[row]);    // warp-uniform broadcast
    out[(size_t)row * EMB_F4 + lane] =
        __ldg(&table[(size_t)src * EMB_F4 + lane]);
}

extern "C" void kernel_launch(void* const* d_in, const int* in_sizes, int n_in,
                              void* d_out, int out_size)
{
    // Identify inputs by element count, independent of ordering:
    // table has 2,000,000*128 = 268,435,456 elements; idx has 1,048,576.
    const void* table_p = d_in[0];
    const void* idx_p   = d_in[1];
    int         idx_n   = in_sizes[1];
    if (n_in >= 2 && in_sizes[0] < in_sizes[1]) {
        table_p = d_in[1];
        idx_p   = d_in[0];
        idx_n   = in_sizes[0];
    }

    const float4* table = (const float4*)table_p;
    const int*    idx   = (const int*)idx_p;
    float4*       out   = (float4*)d_out;

    const int warps_per_block = THREADS / 32;  // 8 rows / block
    const int grid = (idx_n + warps_per_block - 1) / warps_per_block;

    distemb_gather_kernel<<<grid, THREADS>>>(table, idx, out, idx_n);
}

// round 4
// speedup vs baseline: 1.2422x; 1.2422x over previous
#include <cuda_runtime.h>
#include <cstdint>

// DistEmb forward: out[i, :] = table[idx[i], :]
// table: [2e6, 128] fp32 (1 GB), idx: [1,048,576] int32, out: 512 MB fp32.
//
// One warp handles ROWS_PER_WARP=4 rows per pass: 4 warp-uniform idx loads,
// 4 independent 16B gathers per lane (MLP=4 in the L1tex queue), then 4
// streaming stores. Output stores use __stcs (evict-first) so the write
// stream does not evict gathered table rows from L2 — ~26% of gathers are
// duplicate rows and can hit in L2.

static constexpr int EMB_F4        = 32;  // 128 floats = 32 float4
static constexpr int THREADS       = 256; // 8 warps / block
static constexpr int ROWS_PER_WARP = 4;

__global__ __launch_bounds__(THREADS)
void distemb_gather_kernel(const float4* __restrict__ table,
                           const int* __restrict__ idx,
                           float4* __restrict__ out,
                           int num_ids)
{
    const int gwarp = (blockIdx.x * THREADS + threadIdx.x) >> 5;
    const int lane  = threadIdx.x & 31;
    const int row0  = gwarp * ROWS_PER_WARP;
    if (row0 >= num_ids) return;

    if (row0 + ROWS_PER_WARP <= num_ids) {
        // Fast path: 4 rows, fully unrolled, loads batched before stores.
        int src[ROWS_PER_WARP];
#pragma unroll
        for (int r = 0; r < ROWS_PER_WARP; r++)
            src[r] = __ldg(&idx[row0 + r]);        // warp-uniform broadcasts

        float4 v[ROWS_PER_WARP];
#pragma unroll
        for (int r = 0; r < ROWS_PER_WARP; r++)    // 4 independent LDG.128
            v[r] = __ldg(&table[(size_t)src[r] * EMB_F4 + lane]);

#pragma unroll
        for (int r = 0; r < ROWS_PER_WARP; r++)    // streaming, evict-first
            __stcs(&out[(size_t)(row0 + r) * EMB_F4 + lane], v[r]);
    } else {
        for (int r = 0; row0 + r < num_ids; r++) {
            const int src = __ldg(&idx[row0 + r]);
            float4 v = __ldg(&table[(size_t)src * EMB_F4 + lane]);
            __stcs(&out[(size_t)(row0 + r) * EMB_F4 + lane], v);
        }
    }
}

extern "C" void kernel_launch(void* const* d_in, const int* in_sizes, int n_in,
                              void* d_out, int out_size)
{
    // Identify inputs by element count (table: 268,435,456 elems; idx: 1,048,576).
    const void* table_p = d_in[0];
    const void* idx_p   = d_in[1];
    int         idx_n   = in_sizes[1];
    if (n_in >= 2 && in_sizes[0] < in_sizes[1]) {
        table_p = d_in[1];
        idx_p   = d_in[0];
        idx_n   = in_sizes[0];
    }

    const float4* table = (const float4*)table_p;
    const int*    idx   = (const int*)idx_p;
    float4*       out   = (float4*)d_out;

    const int rows_per_block = (THREADS / 32) * ROWS_PER_WARP;  // 32
    const int grid = (idx_n + rows_per_block - 1) / rows_per_block;

    distemb_gather_kernel<<<grid, THREADS>>>(table, idx, out, idx_n);
}